// round 16
// baseline (speedup 1.0000x reference)
#include <cuda_runtime.h>

#define Bn   1024
#define Kseg 160
#define WS   12
#define G    36
#define DH   1024
#define TPAD 168              // Kseg + 8 cp.async overrun pad
#define GT4  (Bn * 12)        // float4 per t slot in g_gi

typedef unsigned long long u64;

// Scratch (static device globals — no allocation)
__device__ float4 g_gi[TPAD * Bn * 12];   // [t][b][c][{r3},{z3},{n3}] (0.5-scaled r,z)
__device__ float4 g_pegi[Kseg * 12];      // [k][c][3] same structure
__device__ float  g_wdecT[Kseg * 4 * 40]; // [k][c][ jloc*12 w..., 36:bias3, pad ]

// Warp-uniform weights -> constant path (prep only)
__constant__ float cWih[G * WS];
__constant__ float cbih[G];
__constant__ float cbhh[G];

__device__ __forceinline__ float ftanh(float x) {
    float y; asm("tanh.approx.f32 %0, %1;" : "=f"(y) : "f"(x)); return y;
}
__device__ __forceinline__ u64 pk(float lo, float hi) {
    u64 r; asm("mov.b64 %0, {%1, %2};" : "=l"(r) : "f"(lo), "f"(hi)); return r;
}
__device__ __forceinline__ void upk(u64 v, float& lo, float& hi) {
    asm("mov.b64 {%0, %1}, %2;" : "=f"(lo), "=f"(hi) : "l"(v));
}
__device__ __forceinline__ u64 ffma2(u64 a, u64 b, u64 c) {
    u64 d; asm("fma.rn.f32x2 %0, %1, %2, %3;" : "=l"(d) : "l"(a), "l"(b), "l"(c));
    return d;
}
__device__ __forceinline__ void cp16(unsigned int d, const float4* s) {
    asm volatile("cp.async.ca.shared.global [%0], [%1], 16;"
                 :: "r"(d), "l"(s) : "memory");
}

// ---------------------------------------------------------------------------
// Prep kernel: 0..639 enc+gi (new layout), 640..799 weff fold (transposed
// per-c layout), 800 pegi.
// ---------------------------------------------------------------------------
__global__ void __launch_bounds__(256) prep_kernel(
        const float* __restrict__ x,
        const float* __restrict__ enc_W,
        const float* __restrict__ enc_b,
        const float* __restrict__ dec_W1,
        const float* __restrict__ dec_b1,
        const float* __restrict__ dec_W2,
        const float* __restrict__ dec_b2) {
    __shared__ float sraw[DH * WS];   // 48 KB

    if (blockIdx.x < 640) {
        float* sEW = sraw;
        float* sEB = sraw + 144;
        float* sg  = sraw + 192;      // 256*37
        int k = blockIdx.x >> 2;
        int bbase = (blockIdx.x & 3) << 8;
        int b = bbase + threadIdx.x;

        {
            int t = threadIdx.x;
            if (t < WS * WS) sEW[t] = enc_W[k * (WS * WS) + t];
            if (t < WS) sEB[t] = enc_b[k * WS + t];
        }
        __syncthreads();

        const float4* xr4 = (const float4*)(x + (size_t)b * 1920 + k * WS);
        float4 x0 = xr4[0], x1 = xr4[1], x2 = xr4[2];
        float xv[WS] = {x0.x, x0.y, x0.z, x0.w, x1.x, x1.y, x1.z, x1.w,
                        x2.x, x2.y, x2.z, x2.w};

        float xs[WS];
#pragma unroll
        for (int o = 0; o < WS; ++o) {
            float a = sEB[o];
#pragma unroll
            for (int i = 0; i < WS; ++i) a = fmaf(xv[i], sEW[i * WS + o], a);
            xs[o] = fmaxf(a, 0.0f);
        }

        float* sgr = sg + threadIdx.x * 37;
#pragma unroll
        for (int g = 0; g < G; ++g) {
            float a = cbih[g] + ((g < 24) ? cbhh[g] : 0.0f);   // fold bhh_r,z
#pragma unroll
            for (int o = 0; o < WS; ++o) a = fmaf(xs[o], cWih[g * WS + o], a);
            sgr[g] = a;
        }
        __syncthreads();

        // write [b][c][gs] float4s: value m = sg[gs*12 + 3c + m], 0.5x for gs<2
        float4* dst = g_gi + ((size_t)k * Bn + bbase) * 12;
        for (int i = threadIdx.x; i < 256 * 12; i += 256) {
            int bl = i / 12;
            int rem = i - bl * 12;
            int cc = rem / 3;
            int gs = rem - cc * 3;
            const float* s = sg + bl * 37 + gs * 12 + cc * 3;
            float sc = (gs < 2) ? 0.5f : 1.0f;
            dst[i] = make_float4(sc * s[0], sc * s[1], sc * s[2], 0.0f);
        }
        return;
    }

    if (blockIdx.x == 800) {
        int k = threadIdx.x;
        if (k >= Kseg) return;
        float pe[WS];
        const float c = -9.210340371976184f / 12.0f;
#pragma unroll
        for (int j = 0; j < 6; ++j) {
            float div = expf(c * (float)(2 * j));
            float ang = (float)k * div;
            pe[2 * j]     = sinf(ang);
            pe[2 * j + 1] = cosf(ang);
        }
        float ch = sinf((float)k);
#pragma unroll
        for (int o = 0; o < WS; ++o) pe[o] += ch;
        float pg[G];
#pragma unroll
        for (int g = 0; g < G; ++g) {
            float a = 0.0f;
#pragma unroll
            for (int o = 0; o < WS; ++o) a = fmaf(pe[o], cWih[g * WS + o], a);
            pg[g] = a;
        }
#pragma unroll
        for (int cc = 0; cc < 4; ++cc)
#pragma unroll
            for (int gs = 0; gs < 3; ++gs) {
                float sc = (gs < 2) ? 0.5f : 1.0f;
                const float* s = pg + gs * 12 + cc * 3;
                g_pegi[k * 12 + cc * 3 + gs] =
                    make_float4(sc * s[0], sc * s[1], sc * s[2], 0.0f);
            }
        return;
    }

    {
        float* w2s = sraw;
        int k = blockIdx.x - 640;
        const float4* W24 = (const float4*)(dec_W2 + (size_t)k * DH * WS);
        float4* w2s4 = (float4*)w2s;
        for (int i = threadIdx.x; i < DH * WS / 4; i += 256) w2s4[i] = W24[i];
        __syncthreads();

        int t = threadIdx.x;
        if (t < 144) {
            int d = t / WS, o = t - (t / WS) * WS;
            const float4* w14 = (const float4*)(dec_W1 + ((size_t)k * WS + d) * DH);
            float a0 = 0.f, a1 = 0.f, a2 = 0.f, a3 = 0.f;
            float a4 = 0.f, a5 = 0.f, a6 = 0.f, a7 = 0.f;
            for (int q = 0; q < DH / 4; q += 2) {
                float4 u = w14[q], v = w14[q + 1];
                int h = q * 4;
                a0 = fmaf(u.x, w2s[(h + 0) * WS + o], a0);
                a1 = fmaf(u.y, w2s[(h + 1) * WS + o], a1);
                a2 = fmaf(u.z, w2s[(h + 2) * WS + o], a2);
                a3 = fmaf(u.w, w2s[(h + 3) * WS + o], a3);
                a4 = fmaf(v.x, w2s[(h + 4) * WS + o], a4);
                a5 = fmaf(v.y, w2s[(h + 5) * WS + o], a5);
                a6 = fmaf(v.z, w2s[(h + 6) * WS + o], a6);
                a7 = fmaf(v.w, w2s[(h + 7) * WS + o], a7);
            }
            int cc = o / 3, jl = o - cc * 3;
            g_wdecT[((size_t)k * 4 + cc) * 40 + jl * 12 + d] =
                ((a0 + a1) + (a2 + a3)) + ((a4 + a5) + (a6 + a7));
        } else if (t < 156) {
            int o = t - 144;
            const float4* b14 = (const float4*)(dec_b1 + (size_t)k * DH);
            float a0 = dec_b2[k * WS + o], a1 = 0.f, a2 = 0.f, a3 = 0.f;
            for (int q = 0; q < DH / 4; ++q) {
                float4 u = b14[q];
                int h = q * 4;
                a0 = fmaf(u.x, w2s[(h + 0) * WS + o], a0);
                a1 = fmaf(u.y, w2s[(h + 1) * WS + o], a1);
                a2 = fmaf(u.z, w2s[(h + 2) * WS + o], a2);
                a3 = fmaf(u.w, w2s[(h + 3) * WS + o], a3);
            }
            int cc = o / 3, jl = o - cc * 3;
            g_wdecT[((size_t)k * 4 + cc) * 40 + 36 + jl] = (a0 + a1) + (a2 + a3);
        }
    }
}

// ---------------------------------------------------------------------------
// RNN + fused decoder. 4 lanes per row, 8 rows per warp: lane (r,c) owns
// h[3c..3c+2]. 12 shfls + 54 FFMA2 per warp-step serve ALL 8 rows. gi comes
// through a depth-8 cp.async smem ring (no ring registers, no barriers —
// per-thread cp.async visibility since each lane copies/reads its own 48B).
// ---------------------------------------------------------------------------
__device__ __forceinline__ void dogates(const u64 hp[6],
                                        float4 G0, float4 G1, float4 G2,
                                        const u64 wRp[3][6], const u64 wZp[3][6],
                                        const u64 wNp[3][6], const float bnp[3],
                                        float hv[3]) {
    float gr[3] = {G0.x, G0.y, G0.z};
    float gz[3] = {G1.x, G1.y, G1.z};
    float gn[3] = {G2.x, G2.y, G2.z};
#pragma unroll
    for (int jl = 0; jl < 3; ++jl) {
        u64 aR = pk(gr[jl], 0.f), aZ = pk(gz[jl], 0.f), aN = pk(bnp[jl], 0.f);
#pragma unroll
        for (int p = 0; p < 6; ++p) {
            aR = ffma2(wRp[jl][p], hp[p], aR);
            aZ = ffma2(wZp[jl][p], hp[p], aZ);
            aN = ffma2(wNp[jl][p], hp[p], aN);
        }
        float rl, rh, zl, zh, nl, nh;
        upk(aR, rl, rh); upk(aZ, zl, zh); upk(aN, nl, nh);
        float r = fmaf(0.5f, ftanh(rl + rh), 0.5f);
        float z = fmaf(0.5f, ftanh(zl + zh), 0.5f);
        float n = ftanh(fmaf(r, nl + nh, gn[jl]));
        hv[jl] = fmaf(z, hv[jl] - n, n);
    }
}

__global__ void __launch_bounds__(32) rnn_kernel(const float* __restrict__ Whh,
                                                 const float* __restrict__ bhh,
                                                 float* __restrict__ out) {
    __shared__ float4 sring[8][32][3];   // 12 KB
    int lane = threadIdx.x;
    int c = lane & 3;
    int row = blockIdx.x * 8 + (lane >> 2);
    int j0 = 3 * c;

    u64 wRp[3][6], wZp[3][6], wNp[3][6];
    float bnp[3];
#pragma unroll
    for (int jl = 0; jl < 3; ++jl) {
        int j = j0 + jl;
#pragma unroll
        for (int p = 0; p < 6; ++p) {
            wRp[jl][p] = pk(0.5f * Whh[j * 12 + 2 * p],        0.5f * Whh[j * 12 + 2 * p + 1]);
            wZp[jl][p] = pk(0.5f * Whh[(12 + j) * 12 + 2 * p], 0.5f * Whh[(12 + j) * 12 + 2 * p + 1]);
            wNp[jl][p] = pk(Whh[(24 + j) * 12 + 2 * p],        Whh[(24 + j) * 12 + 2 * p + 1]);
        }
        bnp[jl] = bhh[24 + j];
    }

    const float4* gbase = g_gi + ((size_t)row * 4 + c) * 3;
    unsigned int sb;
    asm("{ .reg .u64 t; cvta.to.shared.u64 t, %1; cvt.u32.u64 %0, t; }"
        : "=r"(sb) : "l"((const void*)sring));
    sb += lane * 48;

#define ISSUE(slot, tt)                                                     \
    {                                                                       \
        const float4* _s = gbase + (size_t)(tt) * GT4;                      \
        unsigned int _d = sb + (slot) * 1536;                               \
        cp16(_d, _s); cp16(_d + 16, _s + 1); cp16(_d + 32, _s + 2);         \
        asm volatile("cp.async.commit_group;" ::: "memory");                \
    }
#define WAIT7 asm volatile("cp.async.wait_group 7;" ::: "memory")
#define WAIT0 asm volatile("cp.async.wait_group 0;" ::: "memory")

#define GATHER(hp)                                                          \
    {                                                                       \
        float hx[12];                                                       \
        _Pragma("unroll")                                                   \
        for (int c2 = 0; c2 < 4; ++c2) {                                    \
            hx[3 * c2 + 0] = __shfl_sync(0xffffffffu, hv[0], c2, 4);        \
            hx[3 * c2 + 1] = __shfl_sync(0xffffffffu, hv[1], c2, 4);        \
            hx[3 * c2 + 2] = __shfl_sync(0xffffffffu, hv[2], c2, 4);        \
        }                                                                   \
        _Pragma("unroll")                                                   \
        for (int p = 0; p < 6; ++p) hp[p] = pk(hx[2 * p], hx[2 * p + 1]);   \
    }

    float hv[3] = {0.f, 0.f, 0.f};

    // ---------------- phase 1: first GRU ------------------------------------
#pragma unroll
    for (int s = 0; s < 8; ++s) ISSUE(s, s);
    for (int t = 0; t < Kseg; ++t) {
        WAIT7;
        int slot = t & 7;
        float4 G0 = sring[slot][lane][0];
        float4 G1 = sring[slot][lane][1];
        float4 G2 = sring[slot][lane][2];
        u64 hp[6];
        GATHER(hp);
        dogates(hp, G0, G1, G2, wRp, wZp, wNp, bnp, hv);
        ISSUE(slot, t + 8);
    }
    WAIT0;

    // ---------------- phase 2: second GRU + fused decoder -------------------
    float* outp = out + (size_t)row * 1920 + j0;
#pragma unroll
    for (int s = 0; s < 8; ++s) ISSUE(s, s);
    for (int t = 0; t < Kseg; ++t) {
        WAIT7;
        int slot = t & 7;
        float4 G0 = sring[slot][lane][0];
        float4 G1 = sring[slot][lane][1];
        float4 G2 = sring[slot][lane][2];
        const float4* pp = g_pegi + (size_t)t * 12 + c * 3;
        float4 P0 = pp[0], P1 = pp[1], P2 = pp[2];
        G0.x += P0.x; G0.y += P0.y; G0.z += P0.z;
        G1.x += P1.x; G1.y += P1.y; G1.z += P1.z;
        G2.x += P2.x; G2.y += P2.y; G2.z += P2.z;

        u64 hp[6];
        GATHER(hp);

        if (t > 0) {   // decoder output for step t-1 (hp == ys[t-1])
            const float* wb = g_wdecT + ((size_t)(t - 1) * 4 + c) * 40;
            const longlong2* wk = (const longlong2*)wb;
            float4 bb = *(const float4*)(wb + 36);
            float bias[3] = {bb.x, bb.y, bb.z};
#pragma unroll
            for (int jl = 0; jl < 3; ++jl) {
                longlong2 l0 = wk[jl * 3], l1 = wk[jl * 3 + 1], l2 = wk[jl * 3 + 2];
                u64 acc = pk(bias[jl], 0.f);
                acc = ffma2((u64)l0.x, hp[0], acc);
                acc = ffma2((u64)l0.y, hp[1], acc);
                acc = ffma2((u64)l1.x, hp[2], acc);
                acc = ffma2((u64)l1.y, hp[3], acc);
                acc = ffma2((u64)l2.x, hp[4], acc);
                acc = ffma2((u64)l2.y, hp[5], acc);
                float lo, hi; upk(acc, lo, hi);
                outp[(t - 1) * 12 + jl] = lo + hi;
            }
        }

        dogates(hp, G0, G1, G2, wRp, wZp, wNp, bnp, hv);
        ISSUE(slot, t + 8);
    }
    WAIT0;

    // tail: decoder output for t = Kseg-1
    {
        u64 hp[6];
        GATHER(hp);
        const float* wb = g_wdecT + ((size_t)(Kseg - 1) * 4 + c) * 40;
        const longlong2* wk = (const longlong2*)wb;
        float4 bb = *(const float4*)(wb + 36);
        float bias[3] = {bb.x, bb.y, bb.z};
#pragma unroll
        for (int jl = 0; jl < 3; ++jl) {
            longlong2 l0 = wk[jl * 3], l1 = wk[jl * 3 + 1], l2 = wk[jl * 3 + 2];
            u64 acc = pk(bias[jl], 0.f);
            acc = ffma2((u64)l0.x, hp[0], acc);
            acc = ffma2((u64)l0.y, hp[1], acc);
            acc = ffma2((u64)l1.x, hp[2], acc);
            acc = ffma2((u64)l1.y, hp[3], acc);
            acc = ffma2((u64)l2.x, hp[4], acc);
            acc = ffma2((u64)l2.y, hp[5], acc);
            float lo, hi; upk(acc, lo, hi);
            outp[(Kseg - 1) * 12 + jl] = lo + hi;
        }
    }
#undef GATHER
#undef ISSUE
#undef WAIT7
#undef WAIT0
}

// ---------------------------------------------------------------------------
extern "C" void kernel_launch(void* const* d_in, const int* in_sizes, int n_in,
                              void* d_out, int out_size) {
    const float* x     = (const float*)d_in[0];
    const float* enc_W = (const float*)d_in[1];
    const float* enc_b = (const float*)d_in[2];
    const float* Wih   = (const float*)d_in[3];
    const float* Whh   = (const float*)d_in[4];
    const float* bih   = (const float*)d_in[5];
    const float* bhh   = (const float*)d_in[6];
    const float* dW1   = (const float*)d_in[7];
    const float* db1   = (const float*)d_in[8];
    const float* dW2   = (const float*)d_in[9];
    const float* db2   = (const float*)d_in[10];
    float* out = (float*)d_out;

    cudaMemcpyToSymbolAsync(cWih, Wih, G * WS * sizeof(float), 0,
                            cudaMemcpyDeviceToDevice);
    cudaMemcpyToSymbolAsync(cbih, bih, G * sizeof(float), 0,
                            cudaMemcpyDeviceToDevice);
    cudaMemcpyToSymbolAsync(cbhh, bhh, G * sizeof(float), 0,
                            cudaMemcpyDeviceToDevice);

    prep_kernel<<<801, 256>>>(x, enc_W, enc_b, dW1, db1, dW2, db2);
    rnn_kernel<<<128, 32>>>(Whh, bhh, out);   // 8 rows per warp, 4 lanes/row
}

// round 17
// speedup vs baseline: 2.5285x; 2.5285x over previous
#include <cuda_runtime.h>

#define Bn   1024
#define Kseg 160
#define WS   12
#define G    36
#define DH   1024
#define TPAD 168            // Kseg + 8 prefetch pad
#define STR4 (Bn * WS)      // float4 stride between t slots

typedef unsigned long long u64;

// Scratch (static device globals — no allocation)
__device__ float4 g_gi[TPAD * Bn * WS];        // [t][b][j] = {0.5*r, 0.5*z, n_raw, 0}
__device__ float4 g_pegi4[Kseg * WS];          // [k][j] = {0.5*pr, 0.5*pz, pn_raw, 0}
__device__ float4 g_wdec[(Kseg + 2) * WS * 4]; // [k][j][4] (+2 pad k-slots)
__device__ int    g_done;                      // weff-fold completion counter

// Warp-uniform weights -> constant path
__constant__ float cWih[G * WS];
__constant__ float cbih[G];
__constant__ float cbhh[G];

__device__ __forceinline__ float ftanh(float x) {
    float y; asm("tanh.approx.f32 %0, %1;" : "=f"(y) : "f"(x)); return y;
}
__device__ __forceinline__ u64 pk(float lo, float hi) {
    u64 r; asm("mov.b64 %0, {%1, %2};" : "=l"(r) : "f"(lo), "f"(hi)); return r;
}
__device__ __forceinline__ void upk(u64 v, float& lo, float& hi) {
    asm("mov.b64 {%0, %1}, %2;" : "=f"(lo), "=f"(hi) : "l"(v));
}
__device__ __forceinline__ u64 ffma2(u64 a, u64 b, u64 c) {
    u64 d; asm("fma.rn.f32x2 %0, %1, %2, %3;" : "=l"(d) : "l"(a), "l"(b), "l"(c));
    return d;
}
__device__ __forceinline__ float4 ldgcs(const float4* p) {   // streaming load
    float4 v;
    asm("ld.global.cs.v4.f32 {%0,%1,%2,%3}, [%4];"
        : "=f"(v.x), "=f"(v.y), "=f"(v.z), "=f"(v.w) : "l"(p));
    return v;
}

// ---------------------------------------------------------------------------
// Prep kernel: blocks 0..639 = encoder + gi, block 640 = pegi + flag reset.
// (weff fold moved into the rnn launch to overlap its 157 MB DRAM stream.)
// ---------------------------------------------------------------------------
__global__ void __launch_bounds__(256) prep_kernel(
        const float* __restrict__ x,
        const float* __restrict__ enc_W,
        const float* __restrict__ enc_b) {
    __shared__ float sraw[10240];

    if (blockIdx.x < 640) {
        float* sEW = sraw;
        float* sEB = sraw + 144;
        float* sg  = sraw + 192;       // 256*37 = 9472
        int k = blockIdx.x >> 2;
        int bbase = (blockIdx.x & 3) << 8;
        int b = bbase + threadIdx.x;

        {
            int t = threadIdx.x;
            if (t < WS * WS) sEW[t] = enc_W[k * (WS * WS) + t];
            if (t < WS) sEB[t] = enc_b[k * WS + t];
        }
        __syncthreads();

        const float4* xr4 = (const float4*)(x + (size_t)b * 1920 + k * WS);
        float4 x0 = xr4[0], x1 = xr4[1], x2 = xr4[2];
        float xv[WS] = {x0.x, x0.y, x0.z, x0.w, x1.x, x1.y, x1.z, x1.w,
                        x2.x, x2.y, x2.z, x2.w};

        float xs[WS];
#pragma unroll
        for (int o = 0; o < WS; ++o) {
            float a = sEB[o];
#pragma unroll
            for (int i = 0; i < WS; ++i) a = fmaf(xv[i], sEW[i * WS + o], a);
            xs[o] = fmaxf(a, 0.0f);
        }

        float* sgr = sg + threadIdx.x * 37;
#pragma unroll
        for (int g = 0; g < G; ++g) {
            float a = cbih[g] + ((g < 24) ? cbhh[g] : 0.0f);   // fold bhh_r,z
#pragma unroll
            for (int o = 0; o < WS; ++o) a = fmaf(xs[o], cWih[g * WS + o], a);
            sgr[g] = a;
        }
        __syncthreads();

        float4* dst = g_gi + ((size_t)k * Bn + bbase) * WS;
        for (int i = threadIdx.x; i < 256 * WS; i += 256) {
            int bl = i / WS;
            int j = i - bl * WS;
            const float* s = sg + bl * 37;
            dst[i] = make_float4(0.5f * s[j], 0.5f * s[12 + j], s[24 + j], 0.0f);
        }
        return;
    }

    // block 640: pegi table + completion-flag reset
    {
        if (threadIdx.x == 0) g_done = 0;
        int k = threadIdx.x;
        if (k >= Kseg) return;
        float pe[WS];
        const float c = -9.210340371976184f / 12.0f;   // -ln(10000)/d
#pragma unroll
        for (int j = 0; j < 6; ++j) {
            float div = expf(c * (float)(2 * j));
            float ang = (float)k * div;
            pe[2 * j]     = sinf(ang);
            pe[2 * j + 1] = cosf(ang);
        }
        float ch = sinf((float)k);
#pragma unroll
        for (int o = 0; o < WS; ++o) pe[o] += ch;
        float pg[G];
#pragma unroll
        for (int g = 0; g < G; ++g) {
            float a = 0.0f;
#pragma unroll
            for (int o = 0; o < WS; ++o) a = fmaf(pe[o], cWih[g * WS + o], a);
            pg[g] = a;
        }
#pragma unroll
        for (int j = 0; j < WS; ++j)
            g_pegi4[k * WS + j] = make_float4(0.5f * pg[j], 0.5f * pg[12 + j],
                                              pg[24 + j], 0.0f);
    }
}

// ---------------------------------------------------------------------------
// Fused kernel: blocks 0..255 = RNN rows (R14 structure, 2 rows/warp SIMD),
// blocks 256..415 = weff fold streaming 157 MB of decoder weights
// CONCURRENTLY with rnn phase 1. rnn phase 2 gates on g_done == 160.
// ---------------------------------------------------------------------------
__device__ __forceinline__ void bcast2(float h, u64* hp) {
#pragma unroll
    for (int m = 0; m < 6; ++m) {
        float h0 = __shfl_sync(0xffffffffu, h, 2 * m, 16);
        float h1 = __shfl_sync(0xffffffffu, h, 2 * m + 1, 16);
        hp[m] = pk(h0, h1);
    }
}

__device__ __forceinline__ float gates2(const u64* hp, float gr, float gz,
                                        float gn, float bnp,
                                        const u64* wR, const u64* wZ,
                                        const u64* wN, float h) {
    u64 aR = pk(gr, 0.f), aZ = pk(gz, 0.f), aN = pk(bnp, 0.f);
#pragma unroll
    for (int m = 0; m < 6; ++m) {
        aR = ffma2(wR[m], hp[m], aR);
        aZ = ffma2(wZ[m], hp[m], aZ);
        aN = ffma2(wN[m], hp[m], aN);
    }
    float rl, rh, zl, zh, nl, nh;
    upk(aR, rl, rh); upk(aZ, zl, zh); upk(aN, nl, nh);
    float r = fmaf(0.5f, ftanh(rl + rh), 0.5f);        // sigmoid
    float z = fmaf(0.5f, ftanh(zl + zh), 0.5f);
    float n = ftanh(fmaf(r, nl + nh, gn));             // direct tanh
    return fmaf(z, h - n, n);
}

__device__ __forceinline__ float decacc2u(const u64* hp, const u64* W, float be) {
    u64 acc = pk(be, 0.f);
#pragma unroll
    for (int m = 0; m < 6; ++m) acc = ffma2(W[m], hp[m], acc);
    float lo, hi; upk(acc, lo, hi);
    return lo + hi;
}

__global__ void __launch_bounds__(64) rnn_kernel(
        const float* __restrict__ Whh,
        const float* __restrict__ bhh,
        const float* __restrict__ dec_W1,
        const float* __restrict__ dec_b1,
        const float* __restrict__ dec_W2,
        const float* __restrict__ dec_b2,
        float* __restrict__ out) {
    __shared__ float4 smem_u[3072];            // 48 KB union

    // =================== weff-fold blocks (256..415) ========================
    if (blockIdx.x >= 256) {
        int k = blockIdx.x - 256;
        float* w2s = (float*)smem_u;           // 48 KB staging
        const float4* W24 = (const float4*)(dec_W2 + (size_t)k * DH * WS);
        float4* w2s4 = (float4*)w2s;
        for (int i = threadIdx.x; i < DH * WS / 4; i += 64) w2s4[i] = W24[i];
        __syncthreads();

        float* wdecF = (float*)g_wdec;         // [k][j][16] floats
        for (int u = threadIdx.x; u < 156; u += 64) {
            if (u < 144) {
                int d = u / WS, o = u - (u / WS) * WS;
                const float4* w14 =
                    (const float4*)(dec_W1 + ((size_t)k * WS + d) * DH);
                float a0 = 0.f, a1 = 0.f, a2 = 0.f, a3 = 0.f;
                float a4 = 0.f, a5 = 0.f, a6 = 0.f, a7 = 0.f;
                for (int q = 0; q < DH / 4; q += 2) {
                    float4 uu = w14[q], vv = w14[q + 1];
                    int h = q * 4;
                    a0 = fmaf(uu.x, w2s[(h + 0) * WS + o], a0);
                    a1 = fmaf(uu.y, w2s[(h + 1) * WS + o], a1);
                    a2 = fmaf(uu.z, w2s[(h + 2) * WS + o], a2);
                    a3 = fmaf(uu.w, w2s[(h + 3) * WS + o], a3);
                    a4 = fmaf(vv.x, w2s[(h + 4) * WS + o], a4);
                    a5 = fmaf(vv.y, w2s[(h + 5) * WS + o], a5);
                    a6 = fmaf(vv.z, w2s[(h + 6) * WS + o], a6);
                    a7 = fmaf(vv.w, w2s[(h + 7) * WS + o], a7);
                }
                wdecF[((size_t)k * WS + o) * 16 + d] =
                    ((a0 + a1) + (a2 + a3)) + ((a4 + a5) + (a6 + a7));
            } else {
                int o = u - 144;
                const float4* b14 = (const float4*)(dec_b1 + (size_t)k * DH);
                float a0 = dec_b2[k * WS + o], a1 = 0.f, a2 = 0.f, a3 = 0.f;
                for (int q = 0; q < DH / 4; ++q) {
                    float4 uu = b14[q];
                    int h = q * 4;
                    a0 = fmaf(uu.x, w2s[(h + 0) * WS + o], a0);
                    a1 = fmaf(uu.y, w2s[(h + 1) * WS + o], a1);
                    a2 = fmaf(uu.z, w2s[(h + 2) * WS + o], a2);
                    a3 = fmaf(uu.w, w2s[(h + 3) * WS + o], a3);
                }
                wdecF[((size_t)k * WS + o) * 16 + 12] = (a0 + a1) + (a2 + a3);
            }
        }
        __threadfence();
        __syncthreads();
        if (threadIdx.x == 0) atomicAdd(&g_done, 1);
        return;
    }

    // =================== RNN blocks (0..255) ================================
    float4* pegis = smem_u;                    // first 30 KB of the union
    int lane16 = threadIdx.x & 15;
    int row = blockIdx.x * 4 + (threadIdx.x >> 4);   // 0..1023
    bool act = (lane16 < WS);
    int j = act ? lane16 : (WS - 1);

    u64 wR[6], wZ[6], wN[6];
#pragma unroll
    for (int m = 0; m < 6; ++m) {
        wR[m] = pk(0.5f * Whh[j * 12 + 2 * m],        0.5f * Whh[j * 12 + 2 * m + 1]);
        wZ[m] = pk(0.5f * Whh[(12 + j) * 12 + 2 * m], 0.5f * Whh[(12 + j) * 12 + 2 * m + 1]);
        wN[m] = pk(Whh[(24 + j) * 12 + 2 * m],        Whh[(24 + j) * 12 + 2 * m + 1]);
    }
    float bnp = bhh[24 + j];

    for (int i = threadIdx.x; i < Kseg * WS; i += 64) pegis[i] = g_pegi4[i];
    __syncthreads();

    const float4* pA = g_gi + (size_t)row * WS + j;
    float h = 0.0f;

    // ---------------- phase 1: first GRU, 8-deep prefetch ring --------------
    {
        float4 a0 = ldgcs(pA),            a1 = ldgcs(pA + STR4);
        float4 a2 = ldgcs(pA + 2 * STR4), a3 = ldgcs(pA + 3 * STR4);
        float4 a4 = ldgcs(pA + 4 * STR4), a5 = ldgcs(pA + 5 * STR4);
        float4 a6 = ldgcs(pA + 6 * STR4), a7 = ldgcs(pA + 7 * STR4);
        const float4* q = pA + 8 * STR4;
        for (int t = 0; t < Kseg; t += 8) {
            u64 hp[6];
            bcast2(h, hp); h = gates2(hp, a0.x, a0.y, a0.z, bnp, wR, wZ, wN, h);
            a0 = ldgcs(q);
            bcast2(h, hp); h = gates2(hp, a1.x, a1.y, a1.z, bnp, wR, wZ, wN, h);
            a1 = ldgcs(q + STR4);
            bcast2(h, hp); h = gates2(hp, a2.x, a2.y, a2.z, bnp, wR, wZ, wN, h);
            a2 = ldgcs(q + 2 * STR4);
            bcast2(h, hp); h = gates2(hp, a3.x, a3.y, a3.z, bnp, wR, wZ, wN, h);
            a3 = ldgcs(q + 3 * STR4);
            bcast2(h, hp); h = gates2(hp, a4.x, a4.y, a4.z, bnp, wR, wZ, wN, h);
            a4 = ldgcs(q + 4 * STR4);
            bcast2(h, hp); h = gates2(hp, a5.x, a5.y, a5.z, bnp, wR, wZ, wN, h);
            a5 = ldgcs(q + 5 * STR4);
            bcast2(h, hp); h = gates2(hp, a6.x, a6.y, a6.z, bnp, wR, wZ, wN, h);
            a6 = ldgcs(q + 6 * STR4);
            bcast2(h, hp); h = gates2(hp, a7.x, a7.y, a7.z, bnp, wR, wZ, wN, h);
            a7 = ldgcs(q + 7 * STR4);
            q += 8 * STR4;
        }
    }

    // Wait for concurrent weff blocks before touching g_wdec (all co-resident)
    if (threadIdx.x == 0) {
        int v;
        do {
            asm volatile("ld.global.acquire.gpu.s32 %0, [%1];"
                         : "=r"(v) : "l"(&g_done));
            if (v < 160) __nanosleep(200);
        } while (v < 160);
    }
    __syncthreads();

    // ---------------- phase 2: second GRU + fused decoder -------------------
    float* outp = out + (size_t)row * 1920 + j;
    const float4* wgj = g_wdec + (size_t)j * 4;       // + k*48 per step

#define LOADW(W, BIAS, KK)                                                  \
    {                                                                       \
        const longlong2* _p = (const longlong2*)(wgj + (size_t)(KK) * 48);  \
        longlong2 l0 = _p[0], l1 = _p[1], l2 = _p[2];                       \
        W[0] = (u64)l0.x; W[1] = (u64)l0.y;                                 \
        W[2] = (u64)l1.x; W[3] = (u64)l1.y;                                 \
        W[4] = (u64)l2.x; W[5] = (u64)l2.y;                                 \
        BIAS = wgj[(size_t)(KK) * 48 + 3].x;                                \
    }

    u64 WE[6], WO[6];
    float beE, beO;
    LOADW(WE, beE, 0);       // consumed at t=1
    LOADW(WO, beO, 1);       // consumed at t=2

    {
        float4 a0 = ldgcs(pA),            a1 = ldgcs(pA + STR4);
        float4 a2 = ldgcs(pA + 2 * STR4), a3 = ldgcs(pA + 3 * STR4);
        const float4* q = pA + 4 * STR4;
        const float4* pg = pegis + j;

#define STEP2(AREG, PV, TT, QOFF, WB, BB)                                   \
        {                                                                   \
            u64 hp[6];                                                      \
            bcast2(h, hp);                                                  \
            if (act && (TT) > 0) {                                          \
                float oa = decacc2u(hp, WB, BB);                            \
                outp[((TT) - 1) * 12] = oa;                                 \
            }                                                               \
            h = gates2(hp, AREG.x + PV.x, AREG.y + PV.y, AREG.z + PV.z,     \
                       bnp, wR, wZ, wN, h);                                 \
            AREG = ldgcs(q + (QOFF));                                       \
            LOADW(WB, BB, (TT) + 1);                                        \
        }

        for (int t = 0; t < Kseg; t += 4) {
            float4 p0 = pg[0], p1 = pg[WS], p2 = pg[2 * WS], p3 = pg[3 * WS];
            pg += 4 * WS;
            STEP2(a0, p0, t + 0, 0,        WO, beO);
            STEP2(a1, p1, t + 1, STR4,     WE, beE);
            STEP2(a2, p2, t + 2, 2 * STR4, WO, beO);
            STEP2(a3, p3, t + 3, 3 * STR4, WE, beE);
            q += 4 * STR4;
        }
#undef STEP2

        // tail: out for t = Kseg-1 from WO (loaded at step 158)
        u64 hp[6];
        bcast2(h, hp);
        if (act) {
            float oa = decacc2u(hp, WO, beO);
            outp[(Kseg - 1) * 12] = oa;
        }
    }
#undef LOADW
}

// ---------------------------------------------------------------------------
extern "C" void kernel_launch(void* const* d_in, const int* in_sizes, int n_in,
                              void* d_out, int out_size) {
    const float* x     = (const float*)d_in[0];
    const float* enc_W = (const float*)d_in[1];
    const float* enc_b = (const float*)d_in[2];
    const float* Wih   = (const float*)d_in[3];
    const float* Whh   = (const float*)d_in[4];
    const float* bih   = (const float*)d_in[5];
    const float* bhh   = (const float*)d_in[6];
    const float* dW1   = (const float*)d_in[7];
    const float* db1   = (const float*)d_in[8];
    const float* dW2   = (const float*)d_in[9];
    const float* db2   = (const float*)d_in[10];
    float* out = (float*)d_out;

    cudaMemcpyToSymbolAsync(cWih, Wih, G * WS * sizeof(float), 0,
                            cudaMemcpyDeviceToDevice);
    cudaMemcpyToSymbolAsync(cbih, bih, G * sizeof(float), 0,
                            cudaMemcpyDeviceToDevice);
    cudaMemcpyToSymbolAsync(cbhh, bhh, G * sizeof(float), 0,
                            cudaMemcpyDeviceToDevice);

    prep_kernel<<<641, 256>>>(x, enc_W, enc_b);
    rnn_kernel<<<416, 64>>>(Whh, bhh, dW1, db1, dW2, db2, out);
}